// round 2
// baseline (speedup 1.0000x reference)
#include <cuda_runtime.h>
#include <stdint.h>

#define NEG_FILL -1e20f
#define MAXB 8
#define MAXN 16384

// scratch (no allocation allowed)
__device__ int g_topidx[MAXB * MAXN];
__device__ unsigned g_mask_isbyte;

__device__ __forceinline__ unsigned int mono32(float f) {
    unsigned int u = __float_as_uint(f);
    return (u & 0x80000000u) ? ~u : (u | 0x80000000u);
}
__device__ __forceinline__ float inv_mono32(unsigned int k) {
    unsigned int u = (k & 0x80000000u) ? (k ^ 0x80000000u) : ~k;
    return __uint_as_float(u);
}

// mask accessor tolerant of byte-packed (bool) or word-packed (int32/float32)
__device__ __forceinline__ bool mread(const void* m, size_t i, unsigned isbyte) {
    return isbyte ? (((const unsigned char*)m)[i] != 0)
                  : (((const unsigned int*)m)[i] != 0u);
}

// Classify mask storage: any word outside {0, 1, 1.0f-bits} => byte-packed.
__global__ void detect_mask(const unsigned int* __restrict__ m, int words) {
    __shared__ unsigned s_flag;
    if (threadIdx.x == 0) s_flag = 0;
    __syncthreads();
    unsigned f = 0;
    for (int i = threadIdx.x; i < words; i += blockDim.x) {
        unsigned v = m[i];
        if (v != 0u && v != 1u && v != 0x3F800000u) f = 1;
    }
    if (f) atomicOr(&s_flag, 1u);
    __syncthreads();
    if (threadIdx.x == 0) g_mask_isbyte = s_flag;
}

// prob = max over tags 1..7 of softmax over 8 tags == exp(m1-m)/Z
__device__ __forceinline__ float prob8(const float4* p) {
    float4 a = p[0], b = p[1];
    float m1 = fmaxf(fmaxf(a.y, a.z),
                     fmaxf(a.w, fmaxf(fmaxf(b.x, b.y), fmaxf(b.z, b.w))));
    float m = fmaxf(a.x, m1);
    float z = expf(a.x - m) + expf(a.y - m) + expf(a.z - m) + expf(a.w - m)
            + expf(b.x - m) + expf(b.y - m) + expf(b.z - m) + expf(b.w - m);
    return expf(m1 - m) / z;
}

extern __shared__ unsigned long long s_keys[];  // N 46-bit keys

__global__ __launch_bounds__(1024) void spanprune_select(
    const float* __restrict__ scores_a,
    const float* __restrict__ scores_b,
    const void* __restrict__ span_mask,
    const int* __restrict__ seq_length,
    float* __restrict__ out,
    int B, int N, int K, int D)
{
    __shared__ unsigned int s_hist[256];
    __shared__ int s_bcast[2];
    __shared__ int s_scan[1024];
    __shared__ int s_fill;

    const int b = blockIdx.x;
    const int tid = threadIdx.x;
    const int bdim = blockDim.x;
    const unsigned isbyte = g_mask_isbyte;

    const float4* sa = (const float4*)(scores_a + (size_t)b * N * 8);
    const float4* sb = (const float4*)(scores_b + (size_t)b * N * 8);
    const size_t mbase = (size_t)b * N;

    // ---- Phase 1: scores -> monotonic keys (index in low 14 bits, inverted:
    //      larger key == higher score, ties broken by LOWER index) ----
    for (int i = tid; i < N; i += bdim) {
        float pa = prob8(sa + 2 * i);
        float pb = prob8(sb + 2 * i);
        float p = fmaxf(pa, pb);
        float sc = mread(span_mask, mbase + i, isbyte) ? p : NEG_FILL;
        s_keys[i] = ((unsigned long long)mono32(sc) << 14)
                  | (unsigned long long)(N - 1 - i);
    }
    __syncthreads();

    int sl = seq_length[b];
    int num_keep = sl * 2;
    if (num_keep < 1) num_keep = 1;
    if (num_keep > K) num_keep = K;

    // ---- Phase 2: radix-select the num_keep-th and K-th largest keys ----
    unsigned long long thr[2];
    int rwant[2];
    rwant[0] = num_keep;
    rwant[1] = K;

    for (int s = 0; s < 2; ++s) {
        unsigned long long prefix = 0ULL;
        int r = rwant[s];
        for (int shift = 40; shift >= 0; shift -= 8) {
            for (int i = tid; i < 256; i += bdim) s_hist[i] = 0;
            __syncthreads();
            for (int i = tid; i < N; i += bdim) {
                unsigned long long k = s_keys[i];
                if ((k >> (shift + 8)) == prefix)
                    atomicAdd(&s_hist[(unsigned)((k >> shift) & 0xFFULL)], 1u);
            }
            __syncthreads();
            if (tid == 0) {
                int acc = 0, d = 0;
                for (int bin = 255; bin >= 0; --bin) {
                    int c = (int)s_hist[bin];
                    if (acc + c >= r) { d = bin; break; }
                    acc += c;
                }
                s_bcast[0] = d;
                s_bcast[1] = acc;
            }
            __syncthreads();
            prefix = (prefix << 8) | (unsigned long long)s_bcast[0];
            r -= s_bcast[1];
            __syncthreads();
        }
        thr[s] = prefix;  // exact r-th largest key; keys are distinct
    }

    // ---- Phase 3: in-order compaction (keys >= thr[0]) => sorted indices of
    //      top-num_keep. fill = max index among top-K (keys >= thr[1]). ----
    if (tid == 0) s_fill = 0;
    __syncthreads();

    const int CH = N / bdim;  // contiguous chunk per thread keeps n ascending
    int base = tid * CH;
    int cnt = 0, fm = -1;
    for (int i = 0; i < CH; ++i) {
        unsigned long long k = s_keys[base + i];
        if (k >= thr[0]) cnt++;
        if (k >= thr[1]) fm = base + i;
    }
    if (fm >= 0) atomicMax(&s_fill, fm);
    s_scan[tid] = cnt;
    __syncthreads();
    for (int off = 1; off < bdim; off <<= 1) {  // Hillis-Steele inclusive scan
        int v = (tid >= off) ? s_scan[tid - off] : 0;
        __syncthreads();
        s_scan[tid] += v;
        __syncthreads();
    }
    int pos = s_scan[tid] - cnt;  // exclusive prefix
    int* gt = g_topidx + (size_t)b * N;
    for (int i = 0; i < CH; ++i) {
        unsigned long long k = s_keys[base + i];
        if (k >= thr[0]) gt[pos++] = base + i;
    }
    __threadfence_block();
    __syncthreads();
    int fill = s_fill;

    // ---- Phase 4: write idx / scores / mask; finalize gt[] for gather ----
    float* idx_out = out;
    float* sc_out = out + (size_t)B * K * (1 + D);
    float* mk_out = sc_out + (size_t)B * K;
    for (int j = tid; j < K; j += bdim) {
        int idx = (j < num_keep) ? gt[j] : fill;
        gt[j] = idx;
        idx_out[(size_t)b * K + j] = (float)idx;
        unsigned long long kk = s_keys[idx];
        sc_out[(size_t)b * K + j] = inv_mono32((unsigned)(kk >> 14));
        mk_out[(size_t)b * K + j] =
            (j < num_keep && mread(span_mask, mbase + idx, isbyte)) ? 1.0f : 0.0f;
    }
}

__global__ void spanprune_gather(const float* __restrict__ emb,
                                 float* __restrict__ out_emb,
                                 int N, int D, int K, int total_vec)
{
    int t = blockIdx.x * blockDim.x + threadIdx.x;
    if (t >= total_vec) return;
    int per_row = D >> 2;
    int row = t / per_row;
    int c = t - row * per_row;
    int b = row / K;
    int j = row - b * K;
    int idx = g_topidx[b * N + j];
    float4 v = ((const float4*)(emb + ((size_t)b * N + idx) * D))[c];
    ((float4*)(out_emb + (size_t)row * D))[c] = v;
}

extern "C" void kernel_launch(void* const* d_in, const int* in_sizes, int n_in,
                              void* d_out, int out_size)
{
    const float* emb = (const float*)d_in[0];
    const float* sa = (const float*)d_in[1];
    const float* sb = (const float*)d_in[2];
    const void* sm = d_in[3];
    const int* sl = (const int*)d_in[4];

    int B = in_sizes[4];                 // 8
    int BN = in_sizes[3];                // B*N
    int N = BN / B;                      // 16384
    int D = in_sizes[0] / BN;            // 256
    int K = out_size / (B * (D + 3));    // max_keep, data-dependent but fixed

    // classify mask storage (byte-packed bool vs int32/float32 words);
    // scan BN/4 words = the full byte region, or the first quarter of a
    // word region — statistically unambiguous either way.
    detect_mask<<<1, 1024>>>((const unsigned int*)sm, BN / 4);

    size_t smem = (size_t)N * sizeof(unsigned long long);  // 128 KB keys
    cudaFuncSetAttribute(spanprune_select,
                         cudaFuncAttributeMaxDynamicSharedMemorySize,
                         (int)smem);

    spanprune_select<<<B, 1024, smem>>>(sa, sb, sm, sl, (float*)d_out,
                                        B, N, K, D);

    int per_row = D / 4;
    int total_vec = B * K * per_row;
    int threads = 256;
    int blocks = (total_vec + threads - 1) / threads;
    spanprune_gather<<<blocks, threads>>>(emb, (float*)d_out + (size_t)B * K,
                                          N, D, K, total_vec);
}

// round 3
// speedup vs baseline: 1.9491x; 1.9491x over previous
#include <cuda_runtime.h>
#include <stdint.h>

#define NEG_FILL -1e20f
#define MAXB 8
#define MAXN 16384
#define CHUNK 1024

typedef unsigned long long u64;

// scratch (no allocation allowed)
__device__ int g_topidx[MAXB * MAXN];
__device__ u64 g_keys[MAXB * MAXN];

__device__ __forceinline__ unsigned int mono32(float f) {
    unsigned int u = __float_as_uint(f);
    return (u & 0x80000000u) ? ~u : (u | 0x80000000u);
}
__device__ __forceinline__ float inv_mono32(unsigned int k) {
    unsigned int u = (k & 0x80000000u) ? (k ^ 0x80000000u) : ~k;
    return __uint_as_float(u);
}

// prob = max over tags 1..7 of softmax over 8 tags == exp(m1-m)/Z
__device__ __forceinline__ float prob8(const float4* p) {
    float4 a = p[0], b = p[1];
    float m1 = fmaxf(fmaxf(a.y, a.z),
                     fmaxf(a.w, fmaxf(fmaxf(b.x, b.y), fmaxf(b.z, b.w))));
    float m = fmaxf(a.x, m1);
    float z = expf(a.x - m) + expf(a.y - m) + expf(a.z - m) + expf(a.w - m)
            + expf(b.x - m) + expf(b.y - m) + expf(b.z - m) + expf(b.w - m);
    return expf(m1 - m) / z;
}

// ---- Kernel 1: mask-dtype detection (block-local) + prob + 46-bit keys ----
__global__ __launch_bounds__(256) void prob_keys(
    const float4* __restrict__ sa4, const float4* __restrict__ sb4,
    const void* __restrict__ mask, int BN, int Nm1)
{
    __shared__ unsigned s_byte;
    const int i0 = blockIdx.x * CHUNK;
    if (threadIdx.x == 0) s_byte = 0;
    __syncthreads();

    // classify this block's mask window: any word outside {0,1,1.0f} => bytes
    const unsigned* w = (const unsigned*)mask;
    unsigned f = 0;
    for (int j = threadIdx.x; j < CHUNK / 4; j += blockDim.x) {
        unsigned v = w[i0 / 4 + j];
        if (v != 0u && v != 1u && v != 0x3F800000u) f = 1;
    }
    if (f) atomicOr(&s_byte, 1u);
    __syncthreads();
    const unsigned isbyte = s_byte;
    const unsigned char* mb = (const unsigned char*)mask;

    for (int j = threadIdx.x; j < CHUNK; j += blockDim.x) {
        int i = i0 + j;
        if (i >= BN) break;
        float pa = prob8(sa4 + 2 * (size_t)i);
        float pb = prob8(sb4 + 2 * (size_t)i);
        float p = fmaxf(pa, pb);
        bool m = isbyte ? (mb[i] != 0) : (w[i] != 0u);
        float sc = m ? p : NEG_FILL;
        int n = i & Nm1;  // N is a power of 2
        g_keys[i] = ((u64)mono32(sc) << 14) | (u64)(Nm1 - n);
    }
}

// ---- Kernel 2: per-batch two-threshold radix select + ordered compaction ----
extern __shared__ u64 s_keys[];  // N keys, 128 KB

__global__ __launch_bounds__(1024) void spanprune_select(
    const int* __restrict__ seq_length,
    float* __restrict__ out,
    int B, int N, int K, int D)
{
    __shared__ unsigned int s_hist[256];
    __shared__ int s_wsum[32];
    __shared__ int s_bcast[2];
    __shared__ int s_fill;

    const int b = blockIdx.x;
    const int tid = threadIdx.x;
    const int bdim = blockDim.x;
    const int lane = tid & 31;
    const int warp = tid >> 5;

    // load keys (L2-resident, just produced)
    const ulonglong2* kg = (const ulonglong2*)(g_keys + (size_t)b * N);
    for (int i = tid; i < N / 2; i += bdim) {
        ulonglong2 v = kg[i];
        s_keys[2 * i] = v.x;
        s_keys[2 * i + 1] = v.y;
    }
    __syncthreads();

    int sl = seq_length[b];
    int num_keep = sl * 2;
    if (num_keep < 1) num_keep = 1;
    if (num_keep > K) num_keep = K;

    // radix-select the num_keep-th and K-th largest keys (keys all distinct)
    u64 thr[2];
    int rwant[2] = {num_keep, K};

    for (int s = 0; s < 2; ++s) {
        u64 prefix = 0ULL;
        int r = rwant[s];
        for (int shift = 40; shift >= 0; shift -= 8) {
            if (tid < 256) s_hist[tid] = 0;
            __syncthreads();
            for (int i = tid; i < N; i += bdim) {
                u64 k = s_keys[i];
                if ((k >> (shift + 8)) == prefix)
                    atomicAdd(&s_hist[(unsigned)((k >> shift) & 0xFFULL)], 1u);
            }
            __syncthreads();
            // parallel suffix-sum over 256 bins (t ascending == bin descending)
            int v = (tid < 256) ? (int)s_hist[255 - tid] : 0;
            int acc = v;
            #pragma unroll
            for (int o = 1; o < 32; o <<= 1) {
                int x = __shfl_up_sync(0xFFFFFFFFu, acc, o);
                if (lane >= o) acc += x;
            }
            if (lane == 31 && tid < 256) s_wsum[warp] = acc;
            __syncthreads();
            if (tid < 256) {
                int base = 0;
                #pragma unroll
                for (int k = 0; k < 8; ++k)
                    if (k < warp) base += s_wsum[k];
                int S = acc + base;          // count of keys with bin >= (255-tid)
                if (S >= r && S - v < r) {   // unique crossing
                    s_bcast[0] = 255 - tid;  // digit
                    s_bcast[1] = S - v;      // count strictly above
                }
            }
            __syncthreads();
            prefix = (prefix << 8) | (u64)s_bcast[0];
            r -= s_bcast[1];
            __syncthreads();
        }
        thr[s] = prefix;  // exact r-th largest key
    }

    // ordered compaction: keys >= thr[0] in index order => sorted top indices;
    // fill = max index among top-K (keys >= thr[1])
    if (tid == 0) s_fill = 0;
    __syncthreads();

    const int CH = N / bdim;
    int base_i = tid * CH;
    int cnt = 0, fm = -1;
    #pragma unroll 4
    for (int i = 0; i < CH; ++i) {
        u64 k = s_keys[base_i + i];
        if (k >= thr[0]) cnt++;
        if (k >= thr[1]) fm = base_i + i;
    }
    if (fm >= 0) atomicMax(&s_fill, fm);

    // block exclusive scan of cnt (shuffle-based)
    int inc = cnt;
    #pragma unroll
    for (int o = 1; o < 32; o <<= 1) {
        int x = __shfl_up_sync(0xFFFFFFFFu, inc, o);
        if (lane >= o) inc += x;
    }
    if (lane == 31) s_wsum[warp] = inc;
    __syncthreads();
    if (warp == 0) {
        int x = s_wsum[lane];
        #pragma unroll
        for (int o = 1; o < 32; o <<= 1) {
            int y = __shfl_up_sync(0xFFFFFFFFu, x, o);
            if (lane >= o) x += y;
        }
        s_wsum[lane] = x;
    }
    __syncthreads();
    int pos = inc - cnt + (warp > 0 ? s_wsum[warp - 1] : 0);

    int* gt = g_topidx + (size_t)b * N;
    for (int i = 0; i < CH; ++i) {
        u64 k = s_keys[base_i + i];
        if (k >= thr[0]) gt[pos++] = base_i + i;
    }
    __syncthreads();
    int fill = s_fill;

    // write idx / scores / mask; finalize gt[] for gather
    const unsigned negk = mono32(NEG_FILL);
    float* idx_out = out;
    float* sc_out = out + (size_t)B * K * (1 + D);
    float* mk_out = sc_out + (size_t)B * K;
    for (int j = tid; j < K; j += bdim) {
        int idx = (j < num_keep) ? gt[j] : fill;
        gt[j] = idx;
        idx_out[(size_t)b * K + j] = (float)idx;
        unsigned km = (unsigned)(s_keys[idx] >> 14);
        sc_out[(size_t)b * K + j] = inv_mono32(km);
        mk_out[(size_t)b * K + j] = (j < num_keep && km != negk) ? 1.0f : 0.0f;
    }
}

// ---- Kernel 3: embedding gather ----
__global__ __launch_bounds__(256) void spanprune_gather(
    const float* __restrict__ emb, float* __restrict__ out_emb,
    int N, int D, int K, int total_vec)
{
    int t = blockIdx.x * blockDim.x + threadIdx.x;
    if (t >= total_vec) return;
    int per_row = D >> 2;
    int row = t / per_row;
    int c = t - row * per_row;
    int b = row / K;
    int j = row - b * K;
    int idx = g_topidx[b * N + j];
    float4 v = ((const float4*)(emb + ((size_t)b * N + idx) * D))[c];
    ((float4*)(out_emb + (size_t)row * D))[c] = v;
}

extern "C" void kernel_launch(void* const* d_in, const int* in_sizes, int n_in,
                              void* d_out, int out_size)
{
    const float* emb = (const float*)d_in[0];
    const float4* sa = (const float4*)d_in[1];
    const float4* sb = (const float4*)d_in[2];
    const void* sm = d_in[3];
    const int* sl = (const int*)d_in[4];

    int B = in_sizes[4];                 // 8
    int BN = in_sizes[3];                // B*N
    int N = BN / B;                      // 16384
    int D = in_sizes[0] / BN;            // 256
    int K = out_size / (B * (D + 3));    // max_keep

    prob_keys<<<(BN + CHUNK - 1) / CHUNK, 256>>>(sa, sb, sm, BN, N - 1);

    size_t smem = (size_t)N * sizeof(u64);  // 128 KB keys
    cudaFuncSetAttribute(spanprune_select,
                         cudaFuncAttributeMaxDynamicSharedMemorySize,
                         (int)smem);
    spanprune_select<<<B, 1024, smem>>>(sl, (float*)d_out, B, N, K, D);

    int total_vec = B * K * (D / 4);
    int threads = 256;
    int blocks = (total_vec + threads - 1) / threads;
    spanprune_gather<<<blocks, threads>>>(emb, (float*)d_out + (size_t)B * K,
                                          N, D, K, total_vec);
}

// round 4
// speedup vs baseline: 2.1418x; 1.0989x over previous
#include <cuda_runtime.h>
#include <stdint.h>

#define NEG_FILL -1e20f
#define MAXB 8
#define MAXN 16384

typedef unsigned long long u64;
typedef unsigned int u32;
typedef unsigned short u16;

// scratch (no allocation allowed)
__device__ int g_topidx[MAXB * MAXN];
__device__ u32 g_hi[MAXB * MAXN];
__device__ u16 g_lo[MAXB * MAXN];

__device__ __forceinline__ u32 mono32(float f) {
    u32 u = __float_as_uint(f);
    return (u & 0x80000000u) ? ~u : (u | 0x80000000u);
}
__device__ __forceinline__ float inv_mono32(u32 k) {
    u32 u = (k & 0x80000000u) ? (k ^ 0x80000000u) : ~k;
    return __uint_as_float(u);
}

// prob = max over tags 1..7 of softmax over 8 tags == exp(m1-m)/Z
__device__ __forceinline__ float prob8(const float4* p) {
    float4 a = p[0], b = p[1];
    float m1 = fmaxf(fmaxf(a.y, a.z),
                     fmaxf(a.w, fmaxf(fmaxf(b.x, b.y), fmaxf(b.z, b.w))));
    float m = fmaxf(a.x, m1);
    float z = expf(a.x - m) + expf(a.y - m) + expf(a.z - m) + expf(a.w - m)
            + expf(b.x - m) + expf(b.y - m) + expf(b.z - m) + expf(b.w - m);
    return expf(m1 - m) / z;
}

// ---- Kernel 1: mask-dtype detection (block-local) + prob + split keys ----
__global__ __launch_bounds__(256) void prob_keys(
    const float4* __restrict__ sa4, const float4* __restrict__ sb4,
    const void* __restrict__ mask, int BN, int Nm1)
{
    __shared__ unsigned s_byte;
    const int i0 = blockIdx.x * 256;
    if (threadIdx.x == 0) s_byte = 0;
    __syncthreads();

    // classify this block's 64-word mask window: anything outside {0,1,1.0f}
    // means byte-packed bool. (1/8)^64 misclassification probability.
    const u32* w = (const u32*)mask;
    if (threadIdx.x < 64) {
        u32 v = w[i0 / 4 + threadIdx.x];
        if (v != 0u && v != 1u && v != 0x3F800000u) atomicOr(&s_byte, 1u);
    }
    __syncthreads();
    const unsigned isbyte = s_byte;
    const unsigned char* mb = (const unsigned char*)mask;

    int i = i0 + threadIdx.x;
    if (i >= BN) return;
    float pa = prob8(sa4 + 2 * (size_t)i);
    float pb = prob8(sb4 + 2 * (size_t)i);
    float p = fmaxf(pa, pb);
    bool m = isbyte ? (mb[i] != 0) : (w[i] != 0u);
    float sc = m ? p : NEG_FILL;
    int n = i & Nm1;  // N is a power of 2
    g_hi[i] = mono32(sc);
    g_lo[i] = (u16)(Nm1 - n);  // larger lo == smaller index (tie-break)
}

// ---- Kernel 2: per-batch dual-threshold radix select + ordered compaction ----
extern __shared__ char s_dyn[];  // [N*4 hi][N*2 lo] = 96 KB

__global__ __launch_bounds__(1024) void spanprune_select(
    const int* __restrict__ seq_length,
    float* __restrict__ out,
    int B, int N, int K, int D)
{
    __shared__ u32 s_hist[2][256];
    __shared__ int s_wsum[2][8];
    __shared__ int s_bcast[4];  // digit0, above0, digit1, above1
    __shared__ int s_fill;
    __shared__ int s_scanw[32];

    u32* s_hi = (u32*)s_dyn;
    u16* s_lo = (u16*)(s_dyn + (size_t)N * 4);

    const int b = blockIdx.x;
    const int tid = threadIdx.x;
    const int bdim = blockDim.x;
    const int lane = tid & 31;
    const int warp = tid >> 5;

    // load split keys (L2-resident)
    {
        const uint4* gh = (const uint4*)(g_hi + (size_t)b * N);
        for (int i = tid; i < N / 4; i += bdim)
            ((uint4*)s_hi)[i] = gh[i];
        const uint4* gl = (const uint4*)(g_lo + (size_t)b * N);
        for (int i = tid; i < N / 8; i += bdim)
            ((uint4*)s_lo)[i] = gl[i];
    }
    __syncthreads();

    int sl = seq_length[b];
    int num_keep = sl * 2;
    if (num_keep < 1) num_keep = 1;
    if (num_keep > K) num_keep = K;

    u32 pfx[2] = {0u, 0u};
    int r[2] = {num_keep, K};
    bool same = true;

    // ---- hi32 levels: 4 x 8-bit digits ----
    #pragma unroll
    for (int level = 0; level < 4; ++level) {
        const int shift = 24 - 8 * level;
        if (tid < 512) s_hist[tid >> 8][tid & 255] = 0;
        __syncthreads();

        for (int i = tid; i < N; i += bdim) {
            u32 h = s_hi[i];
            #pragma unroll
            for (int s = 0; s < 2; ++s) {
                if (s == 1 && same) break;
                bool ok = (level == 0) || ((h >> (shift + 8)) == pfx[s]);
                u32 msk = __ballot_sync(0xFFFFFFFFu, ok);
                if (ok) {
                    u32 bin = (h >> shift) & 255u;
                    u32 peers = __match_any_sync(msk, bin);
                    if ((int)(__ffs(peers) - 1) == lane)
                        atomicAdd(&s_hist[s][bin], __popc(peers));
                }
            }
        }
        __syncthreads();

        // dual suffix-scan + crossing: group 0 -> r[0], group 1 -> r[1]
        int grp = tid >> 8, t8 = tid & 255;
        if (grp < 2) {
            const u32* hist = s_hist[(grp == 1 && same) ? 0 : grp];
            int v = (int)hist[255 - t8];
            int acc = v;
            #pragma unroll
            for (int o = 1; o < 32; o <<= 1) {
                int x = __shfl_up_sync(0xFFFFFFFFu, acc, o);
                if (lane >= o) acc += x;
            }
            if (lane == 31) s_wsum[grp][(t8 >> 5)] = acc;
            __syncthreads();
            int base = 0;
            #pragma unroll
            for (int k = 0; k < 8; ++k)
                if (k < (t8 >> 5)) base += s_wsum[grp][k];
            int S = acc + base;
            int rr = r[grp];
            if (S >= rr && S - v < rr) {
                s_bcast[2 * grp] = 255 - t8;
                s_bcast[2 * grp + 1] = S - v;
            }
        } else {
            __syncthreads();
        }
        __syncthreads();

        pfx[0] = (pfx[0] << 8) | (u32)s_bcast[0];
        r[0] -= s_bcast[1];
        pfx[1] = (pfx[1] << 8) | (u32)s_bcast[2];
        r[1] -= s_bcast[3];
        same = (pfx[0] == pfx[1]);
        __syncthreads();
    }
    // pfx[s] = exact hi32 of s-th threshold key; r[s] = rank among hi==pfx[s]
    u32 hthr0 = pfx[0], hthr1 = pfx[1];

    // ---- lo14 levels: 2 x 7-bit digits (bins 128) ----
    u32 lpfx[2] = {0u, 0u};
    bool lsame = same;  // identical hi group AND identical r path? only hist sharing needs pfx equality
    #pragma unroll
    for (int level = 0; level < 2; ++level) {
        const int shift = 7 - 7 * level;
        if (tid < 512) s_hist[tid >> 8][tid & 255] = 0;
        __syncthreads();

        for (int i = tid; i < N; i += bdim) {
            u32 h = s_hi[i];
            u32 lo = s_lo[i];
            #pragma unroll
            for (int s = 0; s < 2; ++s) {
                if (s == 1 && lsame) break;
                u32 hs = s ? hthr1 : hthr0;
                bool ok = (h == hs) &&
                          (level == 0 || (lo >> (shift + 7)) == lpfx[s]);
                u32 msk = __ballot_sync(0xFFFFFFFFu, ok);
                if (ok) {
                    u32 bin = (lo >> shift) & 127u;
                    u32 peers = __match_any_sync(msk, bin);
                    if ((int)(__ffs(peers) - 1) == lane)
                        atomicAdd(&s_hist[s][bin], __popc(peers));
                }
            }
        }
        __syncthreads();

        int grp = tid >> 8, t8 = tid & 255;
        if (grp < 2) {
            const u32* hist = s_hist[(grp == 1 && lsame) ? 0 : grp];
            int v = (t8 < 128) ? (int)hist[127 - t8] : 0;
            int acc = v;
            #pragma unroll
            for (int o = 1; o < 32; o <<= 1) {
                int x = __shfl_up_sync(0xFFFFFFFFu, acc, o);
                if (lane >= o) acc += x;
            }
            if (lane == 31) s_wsum[grp][(t8 >> 5)] = acc;
            __syncthreads();
            int base = 0;
            #pragma unroll
            for (int k = 0; k < 8; ++k)
                if (k < (t8 >> 5)) base += s_wsum[grp][k];
            int S = acc + base;
            int rr = r[grp];
            if (t8 < 128 && S >= rr && S - v < rr) {
                s_bcast[2 * grp] = 127 - t8;
                s_bcast[2 * grp + 1] = S - v;
            }
        } else {
            __syncthreads();
        }
        __syncthreads();

        lpfx[0] = (lpfx[0] << 7) | (u32)s_bcast[0];
        r[0] -= s_bcast[1];
        lpfx[1] = (lpfx[1] << 7) | (u32)s_bcast[2];
        r[1] -= s_bcast[3];
        lsame = lsame && (lpfx[0] == lpfx[1]);
        __syncthreads();
    }
    u32 lthr0 = lpfx[0], lthr1 = lpfx[1];

    // ---- ordered compaction: key >= thr0 in index order => sorted top
    //      indices; fill = max index among top-K (key >= thr1) ----
    if (tid == 0) s_fill = 0;
    __syncthreads();

    const int CH = N / bdim;
    int base_i = tid * CH;
    int cnt = 0, fm = -1;
    #pragma unroll 4
    for (int i = 0; i < CH; ++i) {
        u32 h = s_hi[base_i + i];
        u32 lo = s_lo[base_i + i];
        if (h > hthr0 || (h == hthr0 && lo >= lthr0)) cnt++;
        if (h > hthr1 || (h == hthr1 && lo >= lthr1)) fm = base_i + i;
    }
    if (fm >= 0) atomicMax(&s_fill, fm);

    // block exclusive scan of cnt
    int inc = cnt;
    #pragma unroll
    for (int o = 1; o < 32; o <<= 1) {
        int x = __shfl_up_sync(0xFFFFFFFFu, inc, o);
        if (lane >= o) inc += x;
    }
    if (lane == 31) s_scanw[warp] = inc;
    __syncthreads();
    if (warp == 0) {
        int x = s_scanw[lane];
        #pragma unroll
        for (int o = 1; o < 32; o <<= 1) {
            int y = __shfl_up_sync(0xFFFFFFFFu, x, o);
            if (lane >= o) x += y;
        }
        s_scanw[lane] = x;
    }
    __syncthreads();
    int pos = inc - cnt + (warp > 0 ? s_scanw[warp - 1] : 0);

    int* gt = g_topidx + (size_t)b * N;
    for (int i = 0; i < CH; ++i) {
        u32 h = s_hi[base_i + i];
        u32 lo = s_lo[base_i + i];
        if (h > hthr0 || (h == hthr0 && lo >= lthr0)) gt[pos++] = base_i + i;
    }
    __syncthreads();
    int fill = s_fill;

    // ---- write idx / scores / mask; finalize gt[] for gather ----
    const u32 negk = mono32(NEG_FILL);
    float* idx_out = out;
    float* sc_out = out + (size_t)B * K * (1 + D);
    float* mk_out = sc_out + (size_t)B * K;
    for (int j = tid; j < K; j += bdim) {
        int idx = (j < num_keep) ? gt[j] : fill;
        gt[j] = idx;
        idx_out[(size_t)b * K + j] = (float)idx;
        u32 km = s_hi[idx];
        sc_out[(size_t)b * K + j] = inv_mono32(km);
        mk_out[(size_t)b * K + j] = (j < num_keep && km != negk) ? 1.0f : 0.0f;
    }
}

// ---- Kernel 3: embedding gather ----
__global__ __launch_bounds__(256) void spanprune_gather(
    const float* __restrict__ emb, float* __restrict__ out_emb,
    int N, int D, int K, int total_vec)
{
    int t = blockIdx.x * blockDim.x + threadIdx.x;
    if (t >= total_vec) return;
    int per_row = D >> 2;
    int row = t / per_row;
    int c = t - row * per_row;
    int b = row / K;
    int j = row - b * K;
    int idx = g_topidx[b * N + j];
    float4 v = ((const float4*)(emb + ((size_t)b * N + idx) * D))[c];
    ((float4*)(out_emb + (size_t)row * D))[c] = v;
}

extern "C" void kernel_launch(void* const* d_in, const int* in_sizes, int n_in,
                              void* d_out, int out_size)
{
    const float* emb = (const float*)d_in[0];
    const float4* sa = (const float4*)d_in[1];
    const float4* sb = (const float4*)d_in[2];
    const void* sm = d_in[3];
    const int* sl = (const int*)d_in[4];

    int B = in_sizes[4];                 // 8
    int BN = in_sizes[3];                // B*N
    int N = BN / B;                      // 16384
    int D = in_sizes[0] / BN;            // 256
    int K = out_size / (B * (D + 3));    // max_keep

    prob_keys<<<(BN + 255) / 256, 256>>>(sa, sb, sm, BN, N - 1);

    size_t smem = (size_t)N * 6;  // 96 KB split keys
    cudaFuncSetAttribute(spanprune_select,
                         cudaFuncAttributeMaxDynamicSharedMemorySize,
                         (int)smem);
    spanprune_select<<<B, 1024, smem>>>(sl, (float*)d_out, B, N, K, D);

    int total_vec = B * K * (D / 4);
    int threads = 256;
    int blocks = (total_vec + threads - 1) / threads;
    spanprune_gather<<<blocks, threads>>>(emb, (float*)d_out + (size_t)B * K,
                                          N, D, K, total_vec);
}